// round 1
// baseline (speedup 1.0000x reference)
#include <cuda_runtime.h>
#include <math.h>

#define Nn 262144
#define WC 128
#define RR 4
#define OUTD 512
#define IND 512
#define IFACE_D 919
#define CC 1431
#define C4 5724
#define KSPLIT 8
#define KCHUNK 179   /* ceil(1431/8) */
#define JT 45        /* ceil(5724/128) */
#define SB 2048      /* score blocks */
#define EB 64        /* exp-sum blocks per column */
#define CAP 4096
#define KNEED 64

// ---------------- scratch (no cudaMalloc allowed) ----------------
__device__ float g_xw[WC];
__device__ float g_zin[5 * C4];
__device__ float g_h[CC];
__device__ float g_c[CC];
__device__ float g_zpart[KSPLIT * C4];
__device__ float g_iface[IFACE_D];
__device__ float g_kk[5 * WC];          // normalized keys with beta folded in
__device__ float g_scores[5 * Nn];      // [r][n]
__device__ float g_redmax[5 * SB];
__device__ float g_redsum[5 * EB];
__device__ float g_max5[5];
__device__ float g_sum5[5];
__device__ unsigned int g_hist[65536];
__device__ unsigned int g_ncand;
__device__ int g_bstar;
__device__ float g_candv[CAP];
__device__ int g_candi[CAP];

__device__ __forceinline__ float sigf(float x) { return 1.f / (1.f + expf(-x)); }
__device__ __forceinline__ float softplusf(float x) {
    return x > 20.f ? x : log1pf(expf(x));
}

// ---------------- zero scratch + alloc output region ----------------
__global__ void k_zero(float* __restrict__ d_out) {
    int i = blockIdx.x * 256 + threadIdx.x;     // grid 1024*256 = Nn
    if (i < 65536) g_hist[i] = 0u;
    if (i == 0) g_ncand = 0u;
    if (i < Nn) d_out[512 + 5 * Nn + i] = 0.f;  // alloc region
}

// ---------------- usage histogram on top-16 float bits ----------------
__global__ void k_hist(const float* __restrict__ u) {
    int n = blockIdx.x * 256 + threadIdx.x;
    unsigned int b = __float_as_uint(u[n]) >> 16;  // u in [0,1): monotone
    atomicAdd(&g_hist[b], 1u);
}

__global__ void k_thresh() {
    __shared__ unsigned int cs[1024];
    int t = threadIdx.x;
    unsigned int s = 0;
    for (int k = 0; k < 64; k++) s += g_hist[t * 64 + k];
    cs[t] = s;
    __syncthreads();
    if (t == 0) {
        unsigned int run = 0;
        int b = 65535;
        for (int c = 0; c < 1024; c++) {
            if (run + cs[c] >= KNEED) {
                for (int k = 0; k < 64; k++) {
                    run += g_hist[c * 64 + k];
                    if (run >= KNEED) { b = c * 64 + k; break; }
                }
                break;
            }
            run += cs[c];
        }
        g_bstar = b;
    }
}

__global__ void k_collect(const float* __restrict__ u) {
    int n = blockIdx.x * 256 + threadIdx.x;
    float v = u[n];
    if ((int)(__float_as_uint(v) >> 16) <= g_bstar) {
        unsigned int p = atomicAdd(&g_ncand, 1u);
        if (p < CAP) { g_candv[p] = v; g_candi[p] = n; }
    }
}

// exact stable sort of candidates (rank-based), then sequential cumprod.
// cumprod of sorted-ascending uniforms underflows to exactly 0 in fp32 long
// before rank 64, so ranks >= 64 contribute exactly 0 (same as reference fp32).
__global__ void k_alloc(float* __restrict__ d_out) {
    __shared__ float sv[KNEED];
    __shared__ int si[KNEED];
    int n = min((int)g_ncand, CAP);
    for (int i = threadIdx.x; i < n; i += 256) {
        float v = g_candv[i];
        int id = g_candi[i];
        int rank = 0;
        for (int j = 0; j < n; j++) {
            float vj = g_candv[j];
            rank += (vj < v) || (vj == v && g_candi[j] < id);
        }
        if (rank < KNEED) { sv[rank] = v; si[rank] = id; }
    }
    __syncthreads();
    if (threadIdx.x == 0) {
        float* alloc = d_out + 512 + 5 * Nn;
        float cp = 1.f;
        int m = n < KNEED ? n : KNEED;
        for (int j = 0; j < m; j++) {
            alloc[si[j]] = (1.f - sv[j]) * cp;
            cp *= sv[j];
        }
    }
}

// ---------------- head: dense projection ----------------
__global__ void k_xw(const float* __restrict__ x, const float* __restrict__ DK,
                     const float* __restrict__ db) {
    __shared__ float sx[IND];
    int t = threadIdx.x;  // 128 threads
    for (int k = t; k < IND; k += 128) sx[k] = x[k];
    __syncthreads();
    float acc = db[t];
    #pragma unroll 8
    for (int k = 0; k < IND; k++) acc += sx[k] * DK[k * WC + t];
    g_xw[t] = acc;
}

// z_in[t] = seq[t] @ lstm_kernel + lstm_bias, for all 5 steps at once
__global__ void k_zin(const float* __restrict__ Wk, const float* __restrict__ bias,
                      const float* __restrict__ read_v) {
    __shared__ float sq[5 * WC];
    int t = threadIdx.x;  // 128
    for (int i = t; i < 5 * WC; i += 128) {
        int tt = i >> 7, k = i & 127;
        sq[i] = (tt == 0) ? g_xw[k] : read_v[(tt - 1) * WC + k];
    }
    __syncthreads();
    int j = blockIdx.x * 128 + t;  // grid JT
    if (j < C4) {
        float b = bias[j];
        float a0 = b, a1 = b, a2 = b, a3 = b, a4 = b;
        #pragma unroll 4
        for (int k = 0; k < WC; k++) {
            float w = Wk[k * C4 + j];
            a0 += sq[k] * w;
            a1 += sq[128 + k] * w;
            a2 += sq[256 + k] * w;
            a3 += sq[384 + k] * w;
            a4 += sq[512 + k] * w;
        }
        g_zin[0 * C4 + j] = a0; g_zin[1 * C4 + j] = a1; g_zin[2 * C4 + j] = a2;
        g_zin[3 * C4 + j] = a3; g_zin[4 * C4 + j] = a4;
    }
}

// partial h @ lstm_recurrent : grid (JT, KSPLIT), block 128
__global__ void k_zpart(const float* __restrict__ Wr, const float* __restrict__ h) {
    __shared__ float sh[KCHUNK];
    int j = blockIdx.x * 128 + threadIdx.x;
    int kb = blockIdx.y * KCHUNK;
    int cnt = min(KCHUNK, CC - kb);
    for (int k = threadIdx.x; k < cnt; k += 128) sh[k] = h[kb + k];
    __syncthreads();
    if (j < C4) {
        float acc = 0.f;
        const float* w = Wr + (size_t)kb * C4 + j;
        #pragma unroll 4
        for (int k = 0; k < cnt; k++) acc += sh[k] * w[(size_t)k * C4];
        g_zpart[blockIdx.y * C4 + j] = acc;
    }
}

// reduce partials + gate math, in-place h/c update
__global__ void k_combine(int t, const float* __restrict__ cin) {
    int j = blockIdx.x * blockDim.x + threadIdx.x;
    if (j >= CC) return;
    float zi = g_zin[t * C4 + j];
    float zf = g_zin[t * C4 + CC + j];
    float zg = g_zin[t * C4 + 2 * CC + j];
    float zo = g_zin[t * C4 + 3 * CC + j];
    #pragma unroll
    for (int s = 0; s < KSPLIT; s++) {
        zi += g_zpart[s * C4 + j];
        zf += g_zpart[s * C4 + CC + j];
        zg += g_zpart[s * C4 + 2 * CC + j];
        zo += g_zpart[s * C4 + 3 * CC + j];
    }
    float c = sigf(zf) * cin[j] + sigf(zi) * tanhf(zg);
    g_c[j] = c;
    g_h[j] = sigf(zo) * tanhf(c);
}

// out = h@W_output -> d_out[0:512];  iface = h@W_interface -> g_iface
__global__ void k_outiface(const float* __restrict__ Wo, const float* __restrict__ Wi,
                           float* __restrict__ d_out) {
    __shared__ float sh[CC];
    int t = blockIdx.x * 256 + threadIdx.x;  // grid 6
    for (int k = threadIdx.x; k < CC; k += 256) sh[k] = g_h[k];
    __syncthreads();
    if (t < OUTD) {
        float a = 0.f;
        #pragma unroll 4
        for (int k = 0; k < CC; k++) a += sh[k] * Wo[(size_t)k * OUTD + t];
        d_out[t] = a;
    } else if (t < OUTD + IFACE_D) {
        int j = t - OUTD;
        float a = 0.f;
        #pragma unroll 4
        for (int k = 0; k < CC; k++) a += sh[k] * Wi[(size_t)k * IFACE_D + j];
        g_iface[j] = a;
    }
}

// keys: l2norm * (1 + softplus(beta)), folded
__global__ void k_parse() {
    int w = threadIdx.x >> 5, lane = threadIdx.x & 31;  // 160 threads
    if (w >= 5) return;
    const float* src = (w < 4) ? (g_iface + w * WC) : (g_iface + 516);
    float bv = (w < 4) ? g_iface[512 + w] : g_iface[644];
    float4 v = ((const float4*)src)[lane];
    float ss = v.x * v.x + v.y * v.y + v.z * v.z + v.w * v.w;
    #pragma unroll
    for (int o = 16; o; o >>= 1) ss += __shfl_xor_sync(~0u, ss, o);
    float sc = rsqrtf(fmaxf(ss, 1e-12f)) * (1.f + softplusf(bv));
    float4 out = make_float4(v.x * sc, v.y * sc, v.z * sc, v.w * sc);
    ((float4*)g_kk)[w * 32 + lane] = out;
}

// main streaming pass: one warp per row, 16 rows/warp. M read once.
__global__ void k_scores(const float* __restrict__ M) {
    int warp = threadIdx.x >> 5, lane = threadIdx.x & 31;
    int base = (blockIdx.x * 8 + warp) * 16;
    const float4* kkp = (const float4*)g_kk;
    float4 kk[5];
    #pragma unroll
    for (int r = 0; r < 5; r++) kk[r] = kkp[r * 32 + lane];
    float sc[5], mx[5];
    #pragma unroll
    for (int r = 0; r < 5; r++) { sc[r] = 0.f; mx[r] = -1e30f; }
    for (int it = 0; it < 16; it++) {
        int row = base + it;
        float4 m = ((const float4*)M)[(size_t)row * 32 + lane];
        float ss = m.x * m.x + m.y * m.y + m.z * m.z + m.w * m.w;
        #pragma unroll
        for (int o = 16; o; o >>= 1) ss += __shfl_xor_sync(~0u, ss, o);
        float inv = rsqrtf(fmaxf(ss, 1e-12f));
        #pragma unroll
        for (int r = 0; r < 5; r++) {
            float p = m.x * kk[r].x + m.y * kk[r].y + m.z * kk[r].z + m.w * kk[r].w;
            #pragma unroll
            for (int o = 16; o; o >>= 1) p += __shfl_xor_sync(~0u, p, o);
            float s = p * inv;
            if (lane == it) sc[r] = s;
            mx[r] = fmaxf(mx[r], s);
        }
    }
    if (lane < 16) {
        #pragma unroll
        for (int r = 0; r < 5; r++) g_scores[r * Nn + base + lane] = sc[r];
    }
    __shared__ float shm[8 * 5];
    if (lane == 0) {
        #pragma unroll
        for (int r = 0; r < 5; r++) shm[warp * 5 + r] = mx[r];
    }
    __syncthreads();
    if (threadIdx.x < 5) {
        float m = -1e30f;
        for (int w2 = 0; w2 < 8; w2++) m = fmaxf(m, shm[w2 * 5 + threadIdx.x]);
        g_redmax[threadIdx.x * SB + blockIdx.x] = m;
    }
}

__global__ void k_maxr() {
    __shared__ float sh[256];
    for (int r = 0; r < 5; r++) {
        float m = -1e30f;
        for (int i = threadIdx.x; i < SB; i += 256) m = fmaxf(m, g_redmax[r * SB + i]);
        sh[threadIdx.x] = m;
        __syncthreads();
        for (int o = 128; o; o >>= 1) {
            if (threadIdx.x < o) sh[threadIdx.x] = fmaxf(sh[threadIdx.x], sh[threadIdx.x + o]);
            __syncthreads();
        }
        if (threadIdx.x == 0) g_max5[r] = sh[0];
        __syncthreads();
    }
}

// exp in place + block sums. grid (EB, 5)
__global__ void k_expsum() {
    int r = blockIdx.y;
    int base = blockIdx.x * 4096;
    float mx = g_max5[r];
    float s = 0.f;
    #pragma unroll 4
    for (int k = 0; k < 16; k++) {
        int i = base + k * 256 + threadIdx.x;
        float e = expf(g_scores[r * Nn + i] - mx);
        g_scores[r * Nn + i] = e;
        s += e;
    }
    __shared__ float sh[256];
    sh[threadIdx.x] = s;
    __syncthreads();
    for (int o = 128; o; o >>= 1) {
        if (threadIdx.x < o) sh[threadIdx.x] += sh[threadIdx.x + o];
        __syncthreads();
    }
    if (threadIdx.x == 0) g_redsum[r * EB + blockIdx.x] = sh[0];
}

__global__ void k_sumr() {
    if (threadIdx.x < 5) {
        float s = 0.f;
        for (int i = 0; i < EB; i++) s += g_redsum[threadIdx.x * EB + i];
        g_sum5[threadIdx.x] = s;
    }
}

__global__ void k_norm(float* __restrict__ d_out) {
    int n = blockIdx.x * 256 + threadIdx.x;  // grid 1024
    float i0 = 1.f / g_sum5[0], i1 = 1.f / g_sum5[1], i2 = 1.f / g_sum5[2],
          i3 = 1.f / g_sum5[3], i4 = 1.f / g_sum5[4];
    float4 w;
    w.x = g_scores[0 * Nn + n] * i0;
    w.y = g_scores[1 * Nn + n] * i1;
    w.z = g_scores[2 * Nn + n] * i2;
    w.w = g_scores[3 * Nn + n] * i3;
    ((float4*)(d_out + 512))[n] = w;                 // w_read (N,4) row-major
    d_out[512 + 4 * Nn + n] = g_scores[4 * Nn + n] * i4;  // w_write
}

extern "C" void kernel_launch(void* const* d_in, const int* in_sizes, int n_in,
                              void* d_out_v, int out_size) {
    const float* x    = (const float*)d_in[0];
    const float* DK   = (const float*)d_in[1];
    const float* db   = (const float*)d_in[2];
    const float* Wk   = (const float*)d_in[3];
    const float* Wr   = (const float*)d_in[4];
    const float* lb   = (const float*)d_in[5];
    const float* h0   = (const float*)d_in[6];
    const float* c0   = (const float*)d_in[7];
    const float* rv   = (const float*)d_in[8];
    const float* Wo   = (const float*)d_in[9];
    const float* Wi   = (const float*)d_in[10];
    const float* M    = (const float*)d_in[11];
    const float* usage = (const float*)d_in[12];
    float* d_out = (float*)d_out_v;

    float *gh, *gc;
    cudaGetSymbolAddress((void**)&gh, g_h);
    cudaGetSymbolAddress((void**)&gc, g_c);

    // independent alloc path + zeroing
    k_zero<<<1024, 256>>>(d_out);
    k_hist<<<1024, 256>>>(usage);
    k_thresh<<<1, 1024>>>();
    k_collect<<<1024, 256>>>(usage);
    k_alloc<<<1, 256>>>(d_out);

    // head
    k_xw<<<1, 128>>>(x, DK, db);
    k_zin<<<JT, 128>>>(Wk, lb, rv);
    for (int t = 0; t < 5; t++) {
        const float* hp = (t == 0) ? h0 : gh;
        const float* cp = (t == 0) ? c0 : gc;
        dim3 grid(JT, KSPLIT);
        k_zpart<<<grid, 128>>>(Wr, hp);
        k_combine<<<(CC + 255) / 256, 256>>>(t, cp);
    }
    k_outiface<<<6, 256>>>(Wo, Wi, d_out);
    k_parse<<<1, 160>>>();

    // big pass + softmax
    k_scores<<<SB, 256>>>(M);
    k_maxr<<<1, 256>>>();
    dim3 eg(EB, 5);
    k_expsum<<<eg, 256>>>();
    k_sumr<<<1, 32>>>();
    k_norm<<<1024, 256>>>(d_out);
}

// round 3
// speedup vs baseline: 1.9466x; 1.9466x over previous
#include <cuda_runtime.h>
#include <math.h>

#define Nn 262144
#define WC 128
#define RR 4
#define OUTD 512
#define IND 512
#define IFACE_D 919
#define CC 1431
#define C4 5724
#define JT 45        /* ceil(5724/128) */
#define KS2 24       /* recurrent k-splits */
#define CH2 60       /* ceil(1431/24) */
#define KSZ 4        /* zin k-splits (128/32) */
#define KS3 12       /* outiface k-splits */
#define CH3 120      /* ceil(1431/12) */
#define OICOLS 1536  /* 12*128 padded cols (512 out + 919 iface + pad) */
#define SB 2048      /* score blocks */
#define EB 64        /* exp-sum blocks per column */
#define CAP 4096
#define KNEED 64

// ---------------- scratch (no cudaMalloc allowed) ----------------
__device__ float g_xwp[8][WC];
__device__ float g_zinp[KSZ][5 * C4];
__device__ float g_h[CC];
__device__ float g_c[CC];
__device__ float g_zpart[KS2 * C4];
__device__ float g_oip[KS3][OICOLS];
__device__ float g_iface[IFACE_D];
__device__ float g_kk[5 * WC];          // normalized keys with beta folded in
__device__ float g_scores[5 * Nn];      // [r][n]
__device__ float g_redmax[5 * SB];
__device__ float g_redsum[5 * EB];
__device__ float g_max5[5];
__device__ float g_sum5[5];
__device__ unsigned int g_hist[65536];
__device__ unsigned int g_ncand;
__device__ int g_bstar;
__device__ float g_candv[CAP];
__device__ int g_candi[CAP];

__device__ __forceinline__ float sigf(float x) { return 1.f / (1.f + expf(-x)); }
__device__ __forceinline__ float softplusf(float x) {
    return x > 20.f ? x : log1pf(expf(x));
}

// ---------------- zero scratch + alloc output region ----------------
__global__ void k_zero(float* __restrict__ d_out) {
    int i = blockIdx.x * 256 + threadIdx.x;     // grid 1024*256 = Nn
    if (i < 65536) g_hist[i] = 0u;
    if (i == 0) g_ncand = 0u;
    if (i < Nn) d_out[512 + 5 * Nn + i] = 0.f;  // alloc region
}

// ---------------- usage histogram on top-16 float bits ----------------
__global__ void k_hist(const float* __restrict__ u) {
    int n = blockIdx.x * 256 + threadIdx.x;
    unsigned int b = __float_as_uint(u[n]) >> 16;  // u in [0,1): monotone
    atomicAdd(&g_hist[b], 1u);
}

__global__ void k_thresh() {
    __shared__ unsigned int cs[1024];
    int t = threadIdx.x;
    unsigned int s = 0;
    for (int k = 0; k < 64; k++) s += g_hist[t * 64 + k];
    cs[t] = s;
    __syncthreads();
    if (t == 0) {
        unsigned int run = 0;
        int b = 65535;
        for (int c = 0; c < 1024; c++) {
            if (run + cs[c] >= KNEED) {
                for (int k = 0; k < 64; k++) {
                    run += g_hist[c * 64 + k];
                    if (run >= KNEED) { b = c * 64 + k; break; }
                }
                break;
            }
            run += cs[c];
        }
        g_bstar = b;
    }
}

__global__ void k_collect(const float* __restrict__ u) {
    int n = blockIdx.x * 256 + threadIdx.x;
    float v = u[n];
    if ((int)(__float_as_uint(v) >> 16) <= g_bstar) {
        unsigned int p = atomicAdd(&g_ncand, 1u);
        if (p < CAP) { g_candv[p] = v; g_candi[p] = n; }
    }
}

// exact stable sort of candidates (rank-based), then sequential cumprod.
// cumprod of sorted-ascending uniforms underflows to exactly 0 in fp32 long
// before rank 64, so ranks >= 64 contribute exactly 0 (same as reference fp32).
__global__ void k_alloc(float* __restrict__ d_out) {
    __shared__ float sv[KNEED];
    __shared__ int si[KNEED];
    int n = min((int)g_ncand, CAP);
    for (int i = threadIdx.x; i < n; i += 256) {
        float v = g_candv[i];
        int id = g_candi[i];
        int rank = 0;
        for (int j = 0; j < n; j++) {
            float vj = g_candv[j];
            rank += (vj < v) || (vj == v && g_candi[j] < id);
        }
        if (rank < KNEED) { sv[rank] = v; si[rank] = id; }
    }
    __syncthreads();
    if (threadIdx.x == 0) {
        float* alloc = d_out + 512 + 5 * Nn;
        float cp = 1.f;
        int m = n < KNEED ? n : KNEED;
        for (int j = 0; j < m; j++) {
            alloc[si[j]] = (1.f - sv[j]) * cp;
            cp *= sv[j];
        }
    }
}

// ---------------- head: dense projection, k-split 8 ----------------
__global__ void k_xw(const float* __restrict__ x, const float* __restrict__ DK) {
    __shared__ float sx[64];
    int t = threadIdx.x;  // 128 threads, grid 8
    int kb = blockIdx.x * 64;
    if (t < 64) sx[t] = x[kb + t];
    __syncthreads();
    float acc = 0.f;
    #pragma unroll 8
    for (int k = 0; k < 64; k++) acc += sx[k] * DK[(kb + k) * WC + t];
    g_xwp[blockIdx.x][t] = acc;
}

// z_in partials: seq[t] @ lstm_kernel, grid (JT, KSZ)
__global__ void k_zin(const float* __restrict__ Wk, const float* __restrict__ db,
                      const float* __restrict__ read_v) {
    __shared__ float sq[5 * 32];
    int t = threadIdx.x;  // 128
    int kb = blockIdx.y * 32;
    // NOTE: 160 staging entries > 128 threads -> MUST loop (round-2 bug fix)
    for (int i = t; i < 5 * 32; i += 128) {
        int tt = i >> 5, k = (i & 31) + kb;
        if (tt == 0) {
            float a = db[k];
            #pragma unroll
            for (int s = 0; s < 8; s++) a += g_xwp[s][k];
            sq[i] = a;
        } else {
            sq[i] = read_v[(tt - 1) * WC + k];
        }
    }
    __syncthreads();
    int j = blockIdx.x * 128 + t;
    if (j < C4) {
        float a0 = 0.f, a1 = 0.f, a2 = 0.f, a3 = 0.f, a4 = 0.f;
        #pragma unroll 8
        for (int k = 0; k < 32; k++) {
            float w = Wk[(size_t)(kb + k) * C4 + j];
            a0 += sq[k] * w;
            a1 += sq[32 + k] * w;
            a2 += sq[64 + k] * w;
            a3 += sq[96 + k] * w;
            a4 += sq[128 + k] * w;
        }
        g_zinp[blockIdx.y][0 * C4 + j] = a0;
        g_zinp[blockIdx.y][1 * C4 + j] = a1;
        g_zinp[blockIdx.y][2 * C4 + j] = a2;
        g_zinp[blockIdx.y][3 * C4 + j] = a3;
        g_zinp[blockIdx.y][4 * C4 + j] = a4;
    }
}

// partial h @ lstm_recurrent : grid (JT, KS2), block 128
__global__ void k_zpart(const float* __restrict__ Wr, const float* __restrict__ h) {
    __shared__ float sh[CH2];
    int j = blockIdx.x * 128 + threadIdx.x;
    int kb = blockIdx.y * CH2;
    int cnt = min(CH2, CC - kb);
    if (threadIdx.x < cnt) sh[threadIdx.x] = h[kb + threadIdx.x];
    __syncthreads();
    if (j < C4) {
        float acc = 0.f;
        const float* w = Wr + (size_t)kb * C4 + j;
        #pragma unroll 8
        for (int k = 0; k < cnt; k++) acc += sh[k] * w[(size_t)k * C4];
        g_zpart[blockIdx.y * C4 + j] = acc;
    }
}

// reduce partials + gate math, write h/c
__global__ void k_combine(int t, const float* __restrict__ cin,
                          const float* __restrict__ lb) {
    int j = blockIdx.x * blockDim.x + threadIdx.x;
    if (j >= CC) return;
    float zi = lb[j], zf = lb[CC + j], zg = lb[2 * CC + j], zo = lb[3 * CC + j];
    #pragma unroll
    for (int s = 0; s < KSZ; s++) {
        zi += g_zinp[s][t * C4 + j];
        zf += g_zinp[s][t * C4 + CC + j];
        zg += g_zinp[s][t * C4 + 2 * CC + j];
        zo += g_zinp[s][t * C4 + 3 * CC + j];
    }
    #pragma unroll
    for (int s = 0; s < KS2; s++) {
        zi += g_zpart[s * C4 + j];
        zf += g_zpart[s * C4 + CC + j];
        zg += g_zpart[s * C4 + 2 * CC + j];
        zo += g_zpart[s * C4 + 3 * CC + j];
    }
    float c = sigf(zf) * cin[j] + sigf(zi) * tanhf(zg);
    g_c[j] = c;
    g_h[j] = sigf(zo) * tanhf(c);
}

// out/iface partials: grid (12 colblocks, KS3), block 128
__global__ void k_oipart(const float* __restrict__ Wo, const float* __restrict__ Wi) {
    __shared__ float sh[CH3];
    int kb = blockIdx.y * CH3;
    int cnt = min(CH3, CC - kb);
    for (int k = threadIdx.x; k < cnt; k += 128) sh[k] = g_h[kb + k];
    __syncthreads();
    int col = blockIdx.x * 128 + threadIdx.x;
    if (col >= OUTD + IFACE_D) return;
    const float* W;
    int stride, cidx;
    if (col < OUTD) { W = Wo; stride = OUTD; cidx = col; }
    else            { W = Wi; stride = IFACE_D; cidx = col - OUTD; }
    const float* w = W + (size_t)kb * stride + cidx;
    float acc = 0.f;
    #pragma unroll 8
    for (int k = 0; k < cnt; k++) acc += sh[k] * w[(size_t)k * stride];
    g_oip[blockIdx.y][col] = acc;
}

__global__ void k_oireduce(float* __restrict__ d_out) {
    int col = blockIdx.x * 256 + threadIdx.x;  // grid 6
    if (col >= OUTD + IFACE_D) return;
    float a = 0.f;
    #pragma unroll
    for (int s = 0; s < KS3; s++) a += g_oip[s][col];
    if (col < OUTD) d_out[col] = a;
    else g_iface[col - OUTD] = a;
}

// keys: l2norm * (1 + softplus(beta)), folded
__global__ void k_parse() {
    int w = threadIdx.x >> 5, lane = threadIdx.x & 31;  // 160 threads
    if (w >= 5) return;
    const float* src = (w < 4) ? (g_iface + w * WC) : (g_iface + 516);
    float bv = (w < 4) ? g_iface[512 + w] : g_iface[644];
    float4 v = ((const float4*)src)[lane];
    float ss = v.x * v.x + v.y * v.y + v.z * v.z + v.w * v.w;
    #pragma unroll
    for (int o = 16; o; o >>= 1) ss += __shfl_xor_sync(~0u, ss, o);
    float sc = rsqrtf(fmaxf(ss, 1e-12f)) * (1.f + softplusf(bv));
    float4 out = make_float4(v.x * sc, v.y * sc, v.z * sc, v.w * sc);
    ((float4*)g_kk)[w * 32 + lane] = out;
}

// main streaming pass: one warp per 16 rows. M read once.
__global__ void k_scores(const float* __restrict__ M) {
    int warp = threadIdx.x >> 5, lane = threadIdx.x & 31;
    int base = (blockIdx.x * 8 + warp) * 16;
    const float4* kkp = (const float4*)g_kk;
    float4 kk[5];
    #pragma unroll
    for (int r = 0; r < 5; r++) kk[r] = kkp[r * 32 + lane];
    float sc[5], mx[5];
    #pragma unroll
    for (int r = 0; r < 5; r++) { sc[r] = 0.f; mx[r] = -1e30f; }
    for (int it = 0; it < 16; it++) {
        int row = base + it;
        float4 m = ((const float4*)M)[(size_t)row * 32 + lane];
        float ss = m.x * m.x + m.y * m.y + m.z * m.z + m.w * m.w;
        #pragma unroll
        for (int o = 16; o; o >>= 1) ss += __shfl_xor_sync(~0u, ss, o);
        float inv = rsqrtf(fmaxf(ss, 1e-12f));
        #pragma unroll
        for (int r = 0; r < 5; r++) {
            float p = m.x * kk[r].x + m.y * kk[r].y + m.z * kk[r].z + m.w * kk[r].w;
            #pragma unroll
            for (int o = 16; o; o >>= 1) p += __shfl_xor_sync(~0u, p, o);
            float s = p * inv;
            if (lane == it) sc[r] = s;
            mx[r] = fmaxf(mx[r], s);
        }
    }
    if (lane < 16) {
        #pragma unroll
        for (int r = 0; r < 5; r++) g_scores[r * Nn + base + lane] = sc[r];
    }
    __shared__ float shm[8 * 5];
    if (lane == 0) {
        #pragma unroll
        for (int r = 0; r < 5; r++) shm[warp * 5 + r] = mx[r];
    }
    __syncthreads();
    if (threadIdx.x < 5) {
        float m = -1e30f;
        for (int w2 = 0; w2 < 8; w2++) m = fmaxf(m, shm[w2 * 5 + threadIdx.x]);
        g_redmax[threadIdx.x * SB + blockIdx.x] = m;
    }
}

__global__ void k_maxr() {
    __shared__ float sh[256];
    for (int r = 0; r < 5; r++) {
        float m = -1e30f;
        for (int i = threadIdx.x; i < SB; i += 256) m = fmaxf(m, g_redmax[r * SB + i]);
        sh[threadIdx.x] = m;
        __syncthreads();
        for (int o = 128; o; o >>= 1) {
            if (threadIdx.x < o) sh[threadIdx.x] = fmaxf(sh[threadIdx.x], sh[threadIdx.x + o]);
            __syncthreads();
        }
        if (threadIdx.x == 0) g_max5[r] = sh[0];
        __syncthreads();
    }
}

// exp in place + block sums. grid (EB, 5)
__global__ void k_expsum() {
    int r = blockIdx.y;
    int base = blockIdx.x * 4096;
    float mx = g_max5[r];
    float s = 0.f;
    #pragma unroll 4
    for (int k = 0; k < 16; k++) {
        int i = base + k * 256 + threadIdx.x;
        float e = expf(g_scores[r * Nn + i] - mx);
        g_scores[r * Nn + i] = e;
        s += e;
    }
    __shared__ float sh[256];
    sh[threadIdx.x] = s;
    __syncthreads();
    for (int o = 128; o; o >>= 1) {
        if (threadIdx.x < o) sh[threadIdx.x] += sh[threadIdx.x + o];
        __syncthreads();
    }
    if (threadIdx.x == 0) g_redsum[r * EB + blockIdx.x] = sh[0];
}

__global__ void k_sumr() {
    if (threadIdx.x < 5) {
        float s = 0.f;
        for (int i = 0; i < EB; i++) s += g_redsum[threadIdx.x * EB + i];
        g_sum5[threadIdx.x] = s;
    }
}

__global__ void k_norm(float* __restrict__ d_out) {
    int n = blockIdx.x * 256 + threadIdx.x;  // grid 1024
    float i0 = 1.f / g_sum5[0], i1 = 1.f / g_sum5[1], i2 = 1.f / g_sum5[2],
          i3 = 1.f / g_sum5[3], i4 = 1.f / g_sum5[4];
    float4 w;
    w.x = g_scores[0 * Nn + n] * i0;
    w.y = g_scores[1 * Nn + n] * i1;
    w.z = g_scores[2 * Nn + n] * i2;
    w.w = g_scores[3 * Nn + n] * i3;
    ((float4*)(d_out + 512))[n] = w;                 // w_read (N,4) row-major
    d_out[512 + 4 * Nn + n] = g_scores[4 * Nn + n] * i4;  // w_write
}

extern "C" void kernel_launch(void* const* d_in, const int* in_sizes, int n_in,
                              void* d_out_v, int out_size) {
    const float* x    = (const float*)d_in[0];
    const float* DK   = (const float*)d_in[1];
    const float* db   = (const float*)d_in[2];
    const float* Wk   = (const float*)d_in[3];
    const float* Wr   = (const float*)d_in[4];
    const float* lb   = (const float*)d_in[5];
    const float* h0   = (const float*)d_in[6];
    const float* c0   = (const float*)d_in[7];
    const float* rv   = (const float*)d_in[8];
    const float* Wo   = (const float*)d_in[9];
    const float* Wi   = (const float*)d_in[10];
    const float* M    = (const float*)d_in[11];
    const float* usage = (const float*)d_in[12];
    float* d_out = (float*)d_out_v;

    float *gh, *gc;
    cudaGetSymbolAddress((void**)&gh, g_h);
    cudaGetSymbolAddress((void**)&gc, g_c);

    // independent alloc path + zeroing
    k_zero<<<1024, 256>>>(d_out);
    k_hist<<<1024, 256>>>(usage);
    k_thresh<<<1, 1024>>>();
    k_collect<<<1024, 256>>>(usage);
    k_alloc<<<1, 256>>>(d_out);

    // head
    k_xw<<<8, 128>>>(x, DK);
    {
        dim3 zg(JT, KSZ);
        k_zin<<<zg, 128>>>(Wk, db, rv);
    }
    for (int t = 0; t < 5; t++) {
        const float* hp = (t == 0) ? h0 : gh;
        const float* cp = (t == 0) ? c0 : gc;
        dim3 grid(JT, KS2);
        k_zpart<<<grid, 128>>>(Wr, hp);
        k_combine<<<(CC + 255) / 256, 256>>>(t, cp, lb);
    }
    {
        dim3 og(12, KS3);
        k_oipart<<<og, 128>>>(Wo, Wi);
    }
    k_oireduce<<<6, 256>>>(d_out);
    k_parse<<<1, 160>>>();

    // big pass + softmax
    k_scores<<<SB, 256>>>(M);
    k_maxr<<<1, 256>>>();
    dim3 eg(EB, 5);
    k_expsum<<<eg, 256>>>();
    k_sumr<<<1, 32>>>();
    k_norm<<<1024, 256>>>(d_out);
}